// round 4
// baseline (speedup 1.0000x reference)
#include <cuda_runtime.h>
#include <cstdint>

#define BATCH 8
#define SEQ   2048
#define DIM   64
#define PAIR_BASE 20000

// ---------------- device scratch (static globals: allocation-free) ----------
__device__ int    g_row_src[BATCH][SEQ];   // compacted tf row -> source s
__device__ int    g_col_src[BATCH][SEQ];   // compacted active col -> source s
__device__ int    g_row_id[BATCH][SEQ];    // compacted tf row -> token id
__device__ int    g_chead[BATCH][PAIR_BASE]; // id -> (compact col idx + 1), 0 = empty; zero at load, re-zeroed by finalize
__device__ int    g_cnext[BATCH][SEQ];     // chain next (+1), 0 = end
__device__ int    g_nrows[BATCH];          // zero at load; re-zeroed by finalize
__device__ int    g_ncols[BATCH];
__device__ double g_numer;                 // zero at load; re-zeroed by finalize

// ---------------- packed fp32x2 helpers (Blackwell FFMA2) --------------------
typedef unsigned long long u64;
__device__ __forceinline__ u64 splat2(float x) {
    u64 d; asm("mov.b64 %0, {%1, %1};" : "=l"(d) : "f"(x)); return d;
}
__device__ __forceinline__ void ffma2(u64& d, u64 a, u64 b) {
    asm("fma.rn.f32x2 %0, %1, %2, %0;" : "+l"(d) : "l"(a), "l"(b));
}
__device__ __forceinline__ void unpack2(float& lo, float& hi, u64 v) {
    asm("mov.b64 {%0, %1}, %2;" : "=f"(lo), "=f"(hi) : "l"(v));
}

// ---------------- prep: index compaction + col-id chains (no data copy) -----
__global__ void prep_kernel(const int* __restrict__ ids,
                            const unsigned char* __restrict__ tf,
                            const unsigned char* __restrict__ act) {
    const int b  = blockIdx.x >> 3;
    const int s  = ((blockIdx.x & 7) << 8) + threadIdx.x;
    const int gs = b * SEQ + s;
    const int id = ids[gs];
    const unsigned lane = threadIdx.x & 31;
    const unsigned below = (1u << lane) - 1u;

    const bool ht = tf[gs] != 0;
    const unsigned mt = __ballot_sync(0xffffffffu, ht);
    int baset = 0;
    if (lane == 0 && mt) baset = atomicAdd(&g_nrows[b], __popc(mt));
    baset = __shfl_sync(0xffffffffu, baset, 0);
    if (ht) {
        int i = baset + __popc(mt & below);
        g_row_src[b][i] = s;
        g_row_id[b][i]  = id;
    }

    const bool ha = act[gs] != 0;
    const unsigned ma = __ballot_sync(0xffffffffu, ha);
    int basea = 0;
    if (lane == 0 && ma) basea = atomicAdd(&g_ncols[b], __popc(ma));
    basea = __shfl_sync(0xffffffffu, basea, 0);
    if (ha) {
        int i = basea + __popc(ma & below);
        g_col_src[b][i] = s;
        g_cnext[b][i]   = atomicExch(&g_chead[b][id], i + 1);
    }
}

// ---------------- correction: rare positive pairs get -log p + log(1-p) -----
__global__ void correction_kernel(const int* __restrict__ keys, int M,
                                  const float* __restrict__ u,
                                  const float* __restrict__ v) {
    const int b  = blockIdx.x;
    const int nr = g_nrows[b];
    float corr = 0.f;

    for (int r = threadIdx.x; r < nr; r += blockDim.x) {
        const int rid = g_row_id[b][r];
        const int lo_key = rid * PAIR_BASE;
        const int hi_key = lo_key + PAIR_BASE;
        // lower_bound(keys, lo_key)
        int lo = 0, hi = M;
        while (lo < hi) {
            int mid = (lo + hi) >> 1;
            if (keys[mid] < lo_key) lo = mid + 1; else hi = mid;
        }
        const float* ur = u + ((size_t)(b * SEQ + g_row_src[b][r])) * DIM;
        int prev = -1;
        for (int i = lo; i < M; i++) {
            const int k = keys[i];
            if (k >= hi_key) break;
            if (k == prev) continue;   // isin = set membership; skip dup keys
            prev = k;
            const int tgt = k - lo_key;
            int c = g_chead[b][tgt];
            while (c > 0) {
                const int ci = c - 1;
                const float* vc = v + ((size_t)(b * SEQ + g_col_src[b][ci])) * DIM;
                float p = 0.f;
                #pragma unroll
                for (int q = 0; q < DIM; q++) p = fmaf(ur[q], vc[q], p);
                p = fminf(fmaxf(p, 1e-8f), 1.0f - 1e-8f);
                corr += __logf(1.0f - p) - __logf(p);
                c = g_cnext[b][ci];
            }
        }
    }
    #pragma unroll
    for (int o = 16; o; o >>= 1) corr += __shfl_xor_sync(0xffffffffu, corr, o);
    if ((threadIdx.x & 31) == 0 && corr != 0.f) atomicAdd(&g_numer, (double)corr);
}

// ---------------- main: 128x128 tile GEMM (FFMA2) + negative-BCE epilogue ---
// 256 threads, microtile 8 rows x 4 col-pairs, K staged 2x32, gather from u/v.
__global__ __launch_bounds__(256, 2)
void main_kernel(const float* __restrict__ u, const float* __restrict__ v) {
    __shared__ __align__(16) float sU[128][33];    // [row][k], padded
    __shared__ __align__(16) float sVt[32][130];   // [k][col], col-pairs contiguous

    const int b    = blockIdx.z;
    const int nr   = g_nrows[b];
    const int nc   = g_ncols[b];
    const int row0 = blockIdx.y * 128;
    const int col0 = blockIdx.x * 128;
    if (row0 >= nr || col0 >= nc) return;

    const int tid = threadIdx.x;
    const int tx  = tid & 15;
    const int ty  = tid >> 4;

    u64 acc[8][4];
    #pragma unroll
    for (int i = 0; i < 8; i++)
        #pragma unroll
        for (int p = 0; p < 4; p++) acc[i][p] = 0ull;

    // gather source rows once (stale entries beyond nr/nc are in-bounds; masked later)
    const int rr = tid >> 1;
    const int kh = (tid & 1) << 4;
    const int srcR = g_row_src[b][row0 + rr];
    const int srcC = g_col_src[b][col0 + rr];
    const float* uRow = u + ((size_t)(b * SEQ + srcR)) * DIM;
    const float* vRow = v + ((size_t)(b * SEQ + srcC)) * DIM;

    #pragma unroll
    for (int ks = 0; ks < 2; ks++) {
        const int k0 = ks * 32;
        {
            const float4* su = (const float4*)(uRow + k0 + kh);
            const float4* sv = (const float4*)(vRow + k0 + kh);
            #pragma unroll
            for (int q = 0; q < 4; q++) {
                float4 a = su[q];
                sU[rr][kh + 4*q + 0] = a.x; sU[rr][kh + 4*q + 1] = a.y;
                sU[rr][kh + 4*q + 2] = a.z; sU[rr][kh + 4*q + 3] = a.w;
                float4 c = sv[q];
                sVt[kh + 4*q + 0][rr] = c.x; sVt[kh + 4*q + 1][rr] = c.y;
                sVt[kh + 4*q + 2][rr] = c.z; sVt[kh + 4*q + 3][rr] = c.w;
            }
        }
        __syncthreads();

        #pragma unroll 8
        for (int k = 0; k < 32; k++) {
            u64 bv[4];
            #pragma unroll
            for (int p = 0; p < 4; p++)
                bv[p] = *(const u64*)(&sVt[k][2*tx + 32*p]);
            #pragma unroll
            for (int i = 0; i < 8; i++) {
                u64 as = splat2(sU[ty + 16*i][k]);
                #pragma unroll
                for (int p = 0; p < 4; p++)
                    ffma2(acc[i][p], as, bv[p]);
            }
        }
        __syncthreads();
    }

    // ---- epilogue: every supervised pair contributes -log(1-p) ----
    float lsum = 0.f;
    #pragma unroll
    for (int i = 0; i < 8; i++) {
        const int r = row0 + ty + 16*i;
        if (r >= nr) continue;
        #pragma unroll
        for (int p = 0; p < 4; p++) {
            float lo, hi;
            unpack2(lo, hi, acc[i][p]);
            #pragma unroll
            for (int e = 0; e < 2; e++) {
                const int c = col0 + 2*tx + 32*p + e;
                if (c >= nc) continue;
                float pr = e ? hi : lo;
                pr = fminf(fmaxf(pr, 1e-8f), 1.0f - 1e-8f);
                lsum -= __logf(1.0f - pr);
            }
        }
    }
    #pragma unroll
    for (int o = 16; o; o >>= 1) lsum += __shfl_xor_sync(0xffffffffu, lsum, o);
    if ((tid & 31) == 0) atomicAdd(&g_numer, (double)lsum);
}

// ---------------- finalize: result + reset all state for next replay --------
__global__ void finalize_kernel(float* __restrict__ out, int n) {
    // all blocks: zero chain heads (8 * 20000 ints)
    const int total = BATCH * PAIR_BASE;
    int* ch = &g_chead[0][0];
    for (int i = blockIdx.x * blockDim.x + threadIdx.x; i < total;
         i += gridDim.x * blockDim.x)
        ch[i] = 0;

    if (blockIdx.x == 0) {
        __shared__ double s_res;
        if (threadIdx.x == 0) {
            double denom = 0.0;
            #pragma unroll
            for (int b = 0; b < BATCH; b++)
                denom += (double)g_nrows[b] * (double)g_ncols[b];
            s_res = g_numer / (denom + 1e-8);
            g_numer = 0.0;
            #pragma unroll
            for (int b = 0; b < BATCH; b++) { g_nrows[b] = 0; g_ncols[b] = 0; }
        }
        __syncthreads();
        float r = (float)s_res;
        for (int i = threadIdx.x; i < n; i += blockDim.x) out[i] = r;
    }
}

// ---------------- launch ------------------------------------------------------
extern "C" void kernel_launch(void* const* d_in, const int* in_sizes, int n_in,
                              void* d_out, int out_size) {
    const int*           ids  = (const int*)d_in[0];
    const unsigned char* tf   = (const unsigned char*)d_in[1];
    const unsigned char* act  = (const unsigned char*)d_in[2];
    const int*           keys = (const int*)d_in[3];
    const float*         u    = (const float*)d_in[4];
    const float*         v    = (const float*)d_in[5];
    const int M = in_sizes[3];

    prep_kernel<<<64, 256>>>(ids, tf, act);
    correction_kernel<<<BATCH, 256>>>(keys, M, u, v);
    dim3 grid(SEQ / 128, SEQ / 128, BATCH);
    main_kernel<<<grid, 256>>>(u, v);
    finalize_kernel<<<80, 256>>>((float*)d_out, out_size);
}

// round 5
// speedup vs baseline: 1.6785x; 1.6785x over previous
#include <cuda_runtime.h>
#include <cstdint>

#define BATCH 8
#define SEQ   2048
#define DIM   64
#define PAIR_BASE 20000

// ---------------- device scratch (static globals: allocation-free) ----------
__device__ int    g_row_src[BATCH][SEQ];     // compacted tf row -> source s
__device__ int    g_col_src[BATCH][SEQ];     // compacted active col -> source s
__device__ int    g_row_id[BATCH][SEQ];      // compacted tf row -> token id
__device__ int    g_col_id[BATCH][SEQ];      // compacted active col -> token id (for reset)
__device__ int    g_chead[BATCH][PAIR_BASE]; // id -> (compact col idx + 1); zero at load, re-zeroed by finalize
__device__ int    g_cnext[BATCH][SEQ];       // chain next (+1), 0 = end
__device__ int    g_nrows[BATCH];            // zeroed by zero_kernel each launch
__device__ int    g_ncols[BATCH];
__device__ double g_numer;

// ---------------- packed fp32x2 helpers (Blackwell FFMA2) --------------------
typedef unsigned long long u64;
__device__ __forceinline__ u64 splat2(float x) {
    u64 d; asm("mov.b64 %0, {%1, %1};" : "=l"(d) : "f"(x)); return d;
}
__device__ __forceinline__ void ffma2(u64& d, u64 a, u64 b) {
    asm("fma.rn.f32x2 %0, %1, %2, %0;" : "+l"(d) : "l"(a), "l"(b));
}
__device__ __forceinline__ void unpack2(float& lo, float& hi, u64 v) {
    asm("mov.b64 {%0, %1}, %2;" : "=f"(lo), "=f"(hi) : "l"(v));
}

// ---------------- zero: reset counters (17 words) -----------------------------
__global__ void zero_kernel() {
    int t = threadIdx.x;
    if (t < BATCH) { g_nrows[t] = 0; g_ncols[t] = 0; }
    if (t == 0)    g_numer = 0.0;
}

// ---------------- prep: index compaction + col-id chains ---------------------
__global__ void prep_kernel(const int* __restrict__ ids,
                            const unsigned char* __restrict__ tf,
                            const unsigned char* __restrict__ act) {
    const int b  = blockIdx.x >> 3;
    const int s  = ((blockIdx.x & 7) << 8) + threadIdx.x;
    const int gs = b * SEQ + s;
    const int id = ids[gs];
    const unsigned lane = threadIdx.x & 31;
    const unsigned below = (1u << lane) - 1u;

    const bool ht = tf[gs] != 0;
    const unsigned mt = __ballot_sync(0xffffffffu, ht);
    int baset = 0;
    if (lane == 0 && mt) baset = atomicAdd(&g_nrows[b], __popc(mt));
    baset = __shfl_sync(0xffffffffu, baset, 0);
    if (ht) {
        int i = baset + __popc(mt & below);
        g_row_src[b][i] = s;
        g_row_id[b][i]  = id;
    }

    const bool ha = act[gs] != 0;
    const unsigned ma = __ballot_sync(0xffffffffu, ha);
    int basea = 0;
    if (lane == 0 && ma) basea = atomicAdd(&g_ncols[b], __popc(ma));
    basea = __shfl_sync(0xffffffffu, basea, 0);
    if (ha) {
        int i = basea + __popc(ma & below);
        g_col_src[b][i] = s;
        g_col_id[b][i]  = id;
        g_cnext[b][i]   = atomicExch(&g_chead[b][id], i + 1);
    }
}

// ---------------- main: GEMM blocks (z<8) + correction blocks (z==8) --------
// GEMM: 128x128 tile, 256 threads, 8 rows x 4 col-pairs microtile (FFMA2).
// Correction: 256 blocks, 1 thread/row, finds rare positives via sorted-key
// range scan + id->col chains; adds [-log p + log(1-p)] per positive.
__global__ __launch_bounds__(256, 2)
void main_kernel(const float* __restrict__ u, const float* __restrict__ v,
                 const int* __restrict__ keys, int M) {
    __shared__ __align__(16) float sU[128][33];    // [row][k], padded
    __shared__ __align__(16) float sVt[32][130];   // [k][col], col-pairs contiguous

    if (blockIdx.z == BATCH) {
        // ---------- correction path ----------
        const int cb    = blockIdx.y * 16 + blockIdx.x;   // 0..255
        const int b     = cb & 7;
        const int chunk = cb >> 3;                        // 0..31
        const int nr    = g_nrows[b];
        const int r     = chunk + (threadIdx.x << 5);     // covers [0, 8192)
        float corr = 0.f;
        if (r < nr) {
            const int rid    = g_row_id[b][r];
            const int lo_key = rid * PAIR_BASE;
            const int hi_key = lo_key + PAIR_BASE;
            int lo = 0, hi = M;
            while (lo < hi) {                              // lower_bound
                int mid = (lo + hi) >> 1;
                if (__ldg(&keys[mid]) < lo_key) lo = mid + 1; else hi = mid;
            }
            const float* ur = u + ((size_t)(b * SEQ + g_row_src[b][r])) * DIM;
            int prev = -1;
            for (int i = lo; i < M; i++) {
                const int k = __ldg(&keys[i]);
                if (k >= hi_key) break;
                if (k == prev) continue;                   // set semantics (dups)
                prev = k;
                int c = g_chead[b][k - lo_key];
                while (c > 0) {
                    const int ci = c - 1;
                    const float* vc = v + ((size_t)(b * SEQ + g_col_src[b][ci])) * DIM;
                    float p = 0.f;
                    #pragma unroll
                    for (int q = 0; q < DIM; q++) p = fmaf(ur[q], vc[q], p);
                    p = fminf(fmaxf(p, 1e-8f), 1.0f - 1e-8f);
                    corr += __logf(1.0f - p) - __logf(p);
                    c = g_cnext[b][ci];
                }
            }
        }
        #pragma unroll
        for (int o = 16; o; o >>= 1) corr += __shfl_xor_sync(0xffffffffu, corr, o);
        if ((threadIdx.x & 31) == 0 && corr != 0.f) atomicAdd(&g_numer, (double)corr);
        return;
    }

    // ---------- GEMM path ----------
    const int b    = blockIdx.z;
    const int nr   = g_nrows[b];
    const int nc   = g_ncols[b];
    const int row0 = blockIdx.y * 128;
    const int col0 = blockIdx.x * 128;
    if (row0 >= nr || col0 >= nc) return;

    const int tid = threadIdx.x;
    const int tx  = tid & 15;
    const int ty  = tid >> 4;

    u64 acc[8][4];
    #pragma unroll
    for (int i = 0; i < 8; i++)
        #pragma unroll
        for (int p = 0; p < 4; p++) acc[i][p] = 0ull;

    const int rr = tid >> 1;
    const int kh = (tid & 1) << 4;
    const int srcR = g_row_src[b][row0 + rr];
    const int srcC = g_col_src[b][col0 + rr];
    const float* uRow = u + ((size_t)(b * SEQ + srcR)) * DIM;
    const float* vRow = v + ((size_t)(b * SEQ + srcC)) * DIM;

    #pragma unroll
    for (int ks = 0; ks < 2; ks++) {
        const int k0 = ks * 32;
        {
            const float4* su = (const float4*)(uRow + k0 + kh);
            const float4* sv = (const float4*)(vRow + k0 + kh);
            #pragma unroll
            for (int q = 0; q < 4; q++) {
                float4 a = su[q];
                sU[rr][kh + 4*q + 0] = a.x; sU[rr][kh + 4*q + 1] = a.y;
                sU[rr][kh + 4*q + 2] = a.z; sU[rr][kh + 4*q + 3] = a.w;
                float4 c = sv[q];
                sVt[kh + 4*q + 0][rr] = c.x; sVt[kh + 4*q + 1][rr] = c.y;
                sVt[kh + 4*q + 2][rr] = c.z; sVt[kh + 4*q + 3][rr] = c.w;
            }
        }
        __syncthreads();

        #pragma unroll 8
        for (int k = 0; k < 32; k++) {
            u64 bv[4];
            #pragma unroll
            for (int p = 0; p < 4; p++)
                bv[p] = *(const u64*)(&sVt[k][2*tx + 32*p]);
            #pragma unroll
            for (int i = 0; i < 8; i++) {
                u64 as = splat2(sU[ty + 16*i][k]);
                #pragma unroll
                for (int p = 0; p < 4; p++)
                    ffma2(acc[i][p], as, bv[p]);
            }
        }
        __syncthreads();
    }

    // ---- epilogue: every supervised pair contributes -log(1-p) ----
    float lsum = 0.f;
    #pragma unroll
    for (int i = 0; i < 8; i++) {
        const int r = row0 + ty + 16*i;
        if (r >= nr) continue;
        #pragma unroll
        for (int p = 0; p < 4; p++) {
            float lo, hi;
            unpack2(lo, hi, acc[i][p]);
            #pragma unroll
            for (int e = 0; e < 2; e++) {
                const int c = col0 + 2*tx + 32*p + e;
                if (c >= nc) continue;
                float pr = e ? hi : lo;
                pr = fminf(fmaxf(pr, 1e-8f), 1.0f - 1e-8f);
                lsum -= __logf(1.0f - pr);
            }
        }
    }
    #pragma unroll
    for (int o = 16; o; o >>= 1) lsum += __shfl_xor_sync(0xffffffffu, lsum, o);
    if ((tid & 31) == 0) atomicAdd(&g_numer, (double)lsum);
}

// ---------------- finalize: targeted chain reset + result -------------------
__global__ void finalize_kernel(float* __restrict__ out, int n) {
    const int b = blockIdx.x;   // 8 blocks
    const int nc = g_ncols[b];
    for (int i = threadIdx.x; i < nc; i += blockDim.x)
        g_chead[b][g_col_id[b][i]] = 0;

    if (b == 0) {
        __shared__ double s_res;
        if (threadIdx.x == 0) {
            double denom = 0.0;
            #pragma unroll
            for (int q = 0; q < BATCH; q++)
                denom += (double)g_nrows[q] * (double)g_ncols[q];
            s_res = g_numer / (denom + 1e-8);
        }
        __syncthreads();
        float r = (float)s_res;
        for (int i = threadIdx.x; i < n; i += blockDim.x) out[i] = r;
    }
}

// ---------------- launch ------------------------------------------------------
extern "C" void kernel_launch(void* const* d_in, const int* in_sizes, int n_in,
                              void* d_out, int out_size) {
    const int*           ids  = (const int*)d_in[0];
    const unsigned char* tf   = (const unsigned char*)d_in[1];
    const unsigned char* act  = (const unsigned char*)d_in[2];
    const int*           keys = (const int*)d_in[3];
    const float*         u    = (const float*)d_in[4];
    const float*         v    = (const float*)d_in[5];
    const int M = in_sizes[3];

    zero_kernel<<<1, 32>>>();
    prep_kernel<<<64, 256>>>(ids, tf, act);
    dim3 grid(SEQ / 128, SEQ / 128, BATCH + 1);   // z==8 -> correction blocks
    main_kernel<<<grid, 256>>>(u, v, keys, M);
    finalize_kernel<<<BATCH, 256>>>((float*)d_out, out_size);
}

// round 8
// speedup vs baseline: 2.0374x; 1.2138x over previous
#include <cuda_runtime.h>
#include <cuda_bf16.h>
#include <cstdint>

#define BATCH 8
#define SEQ   2048
#define DIM   64
#define PAIR_BASE 20000
#define SR2   40   // bf16 smem row pitch per 32-K chunk (32 + 8 pad; 80B rows, 16B aligned)

// ---------------- device scratch (static globals: allocation-free) ----------
__device__ int    g_row_src[BATCH][SEQ];
__device__ int    g_col_src[BATCH][SEQ];
__device__ int    g_row_id[BATCH][SEQ];
__device__ int    g_col_id[BATCH][SEQ];
__device__ int    g_chead[BATCH][PAIR_BASE]; // zero at load; re-zeroed by finalize
__device__ int    g_cnext[BATCH][SEQ];
__device__ int    g_nrows[BATCH];            // zero at load; re-zeroed by finalize
__device__ int    g_ncols[BATCH];
__device__ double g_numer;                   // zero at load; re-zeroed by finalize

__device__ __forceinline__ uint32_t smem_u32(const void* p) {
    uint32_t a;
    asm("{ .reg .u64 t; cvta.to.shared.u64 t, %1; cvt.u32.u64 %0, t; }" : "=r"(a) : "l"(p));
    return a;
}
__device__ __forceinline__ void ldmatrix_x4(uint32_t* r, uint32_t addr) {
    asm volatile("ldmatrix.sync.aligned.m8n8.x4.shared.b16 {%0,%1,%2,%3}, [%4];"
        : "=r"(r[0]), "=r"(r[1]), "=r"(r[2]), "=r"(r[3]) : "r"(addr));
}
// NON-trans x2: with B stored [n][k], lane l gets Bmem[row=l/4][col=(l%4)*2+e]
// == exactly the mma.m16n8k16 col-major B fragment (n=t/4, k=(t%4)*2+e).
__device__ __forceinline__ void ldmatrix_x2(uint32_t* r, uint32_t addr) {
    asm volatile("ldmatrix.sync.aligned.m8n8.x2.shared.b16 {%0,%1}, [%2];"
        : "=r"(r[0]), "=r"(r[1]) : "r"(addr));
}
__device__ __forceinline__ void mma_bf16(float* c, const uint32_t* a, const uint32_t* b) {
    asm volatile("mma.sync.aligned.m16n8k16.row.col.f32.bf16.bf16.f32 "
        "{%0,%1,%2,%3}, {%4,%5,%6,%7}, {%8,%9}, {%0,%1,%2,%3};"
        : "+f"(c[0]), "+f"(c[1]), "+f"(c[2]), "+f"(c[3])
        : "r"(a[0]), "r"(a[1]), "r"(a[2]), "r"(a[3]), "r"(b[0]), "r"(b[1]));
}
// split x into bf16 hi + bf16 lo
__device__ __forceinline__ void split_store(__nv_bfloat16* hi, __nv_bfloat16* lo, float x) {
    __nv_bfloat16 h = __float2bfloat16_rn(x);
    *hi = h;
    *lo = __float2bfloat16_rn(x - __bfloat162float(h));
}

// ---------------- prep: index compaction + col-id chains ---------------------
__global__ void prep_kernel(const int* __restrict__ ids,
                            const unsigned char* __restrict__ tf,
                            const unsigned char* __restrict__ act) {
    const int b  = blockIdx.x >> 3;
    const int s  = ((blockIdx.x & 7) << 8) + threadIdx.x;
    const int gs = b * SEQ + s;
    const int id = ids[gs];
    const unsigned lane = threadIdx.x & 31;
    const unsigned below = (1u << lane) - 1u;

    const bool ht = tf[gs] != 0;
    const unsigned mt = __ballot_sync(0xffffffffu, ht);
    int baset = 0;
    if (lane == 0 && mt) baset = atomicAdd(&g_nrows[b], __popc(mt));
    baset = __shfl_sync(0xffffffffu, baset, 0);
    if (ht) {
        int i = baset + __popc(mt & below);
        g_row_src[b][i] = s;
        g_row_id[b][i]  = id;
    }

    const bool ha = act[gs] != 0;
    const unsigned ma = __ballot_sync(0xffffffffu, ha);
    int basea = 0;
    if (lane == 0 && ma) basea = atomicAdd(&g_ncols[b], __popc(ma));
    basea = __shfl_sync(0xffffffffu, basea, 0);
    if (ha) {
        int i = basea + __popc(ma & below);
        g_col_src[b][i] = s;
        g_col_id[b][i]  = id;
        g_cnext[b][i]   = atomicExch(&g_chead[b][id], i + 1);
    }
}

// ---------------- main: correction (z==0) + split-bf16 HMMA GEMM (z>=1) -----
__global__ __launch_bounds__(256, 2)
void main_kernel(const float* __restrict__ u, const float* __restrict__ v,
                 const int* __restrict__ keys, int M) {
    __shared__ __align__(16) __nv_bfloat16 sAh[128 * SR2];
    __shared__ __align__(16) __nv_bfloat16 sAl[128 * SR2];
    __shared__ __align__(16) __nv_bfloat16 sBh[128 * SR2];
    __shared__ __align__(16) __nv_bfloat16 sBl[128 * SR2];
    __shared__ float wsum[8];

    if (blockIdx.z == 0) {
        // ---------- correction: rare positives get [-log p + log(1-p)] ----------
        const int cb    = blockIdx.y * 16 + blockIdx.x;   // 0..255
        const int b     = cb & 7;
        const int chunk = cb >> 3;                        // 0..31
        const int nr    = g_nrows[b];
        const int r     = chunk + (threadIdx.x << 5);
        float corr = 0.f;
        if (r < nr) {
            const int rid    = g_row_id[b][r];
            const int lo_key = rid * PAIR_BASE;
            const int hi_key = lo_key + PAIR_BASE;
            int lo = 0, hi = M;
            while (lo < hi) {
                int mid = (lo + hi) >> 1;
                if (__ldg(&keys[mid]) < lo_key) lo = mid + 1; else hi = mid;
            }
            const float* ur = u + ((size_t)(b * SEQ + g_row_src[b][r])) * DIM;
            int prev = -1;
            for (int i = lo; i < M; i++) {
                const int k = __ldg(&keys[i]);
                if (k >= hi_key) break;
                if (k == prev) continue;     // set semantics (duplicate keys)
                prev = k;
                int c = g_chead[b][k - lo_key];
                while (c > 0) {
                    const int ci = c - 1;
                    const float* vc = v + ((size_t)(b * SEQ + g_col_src[b][ci])) * DIM;
                    float p = 0.f;
                    #pragma unroll
                    for (int q = 0; q < DIM; q++) p = fmaf(ur[q], vc[q], p);
                    p = fminf(fmaxf(p, 1e-8f), 1.0f - 1e-8f);
                    corr += __logf(1.0f - p) - __logf(p);
                    c = g_cnext[b][ci];
                }
            }
        }
        #pragma unroll
        for (int o = 16; o; o >>= 1) corr += __shfl_xor_sync(0xffffffffu, corr, o);
        if ((threadIdx.x & 31) == 0 && corr != 0.f) atomicAdd(&g_numer, (double)corr);
        return;
    }

    // ---------- GEMM path: 128x128 tile, split-bf16 3-pass mma.sync ----------
    const int b    = blockIdx.z - 1;
    const int nr   = g_nrows[b];
    const int nc   = g_ncols[b];
    const int row0 = blockIdx.y * 128;
    const int col0 = blockIdx.x * 128;
    if (row0 >= nr || col0 >= nc) return;

    const int tid  = threadIdx.x;
    const int wid  = tid >> 5;
    const int lane = tid & 31;

    // warp tiling: 2 (M) x 4 (N) warps; warp tile 64x32
    const int wm = wid & 1, wn = wid >> 1;
    const int m_base = wm * 64, n_base = wn * 32;

    const uint32_t offA = (uint32_t)(((m_base + (lane & 15)) * SR2 + ((lane >> 4) << 3)) * 2);
    const uint32_t offB = (uint32_t)(((n_base + (lane & 7))  * SR2 + (((lane >> 3) & 1) << 3)) * 2);
    const uint32_t aH = smem_u32(sAh) + offA, aL = smem_u32(sAl) + offA;
    const uint32_t bH = smem_u32(sBh) + offB, bL = smem_u32(sBl) + offB;

    // staging pointers (stale rows beyond nr/nc are in-bounds; masked in epilogue)
    const int rr = tid >> 1;
    const int hf = (tid & 1) << 4;   // 0 or 16 floats within 32-chunk
    const float* uR = u + ((size_t)(b * SEQ + g_row_src[b][row0 + rr])) * DIM + hf;
    const float* vR = v + ((size_t)(b * SEQ + g_col_src[b][col0 + rr])) * DIM + hf;

    float acc[4][4][4];
    #pragma unroll
    for (int mi = 0; mi < 4; mi++)
        #pragma unroll
        for (int ni = 0; ni < 4; ni++)
            #pragma unroll
            for (int q = 0; q < 4; q++) acc[mi][ni][q] = 0.f;

    #pragma unroll
    for (int kc = 0; kc < 2; kc++) {
        // ---- stage chunk kc: convert fp32 -> bf16 hi/lo tiles ----
        {
            const int base = rr * SR2 + hf;
            #pragma unroll
            for (int q = 0; q < 4; q++) {
                float4 a = ((const float4*)(uR + kc * 32))[q];
                split_store(&sAh[base + 4*q + 0], &sAl[base + 4*q + 0], a.x);
                split_store(&sAh[base + 4*q + 1], &sAl[base + 4*q + 1], a.y);
                split_store(&sAh[base + 4*q + 2], &sAl[base + 4*q + 2], a.z);
                split_store(&sAh[base + 4*q + 3], &sAl[base + 4*q + 3], a.w);
                float4 c = ((const float4*)(vR + kc * 32))[q];
                split_store(&sBh[base + 4*q + 0], &sBl[base + 4*q + 0], c.x);
                split_store(&sBh[base + 4*q + 1], &sBl[base + 4*q + 1], c.y);
                split_store(&sBh[base + 4*q + 2], &sBl[base + 4*q + 2], c.z);
                split_store(&sBh[base + 4*q + 3], &sBl[base + 4*q + 3], c.w);
            }
        }
        __syncthreads();

        #pragma unroll
        for (int kk = 0; kk < 2; kk++) {
            const uint32_t koff = (uint32_t)(kk * 16 * 2);
            uint32_t ah[4][4], bh[4][2];
            #pragma unroll
            for (int mi = 0; mi < 4; mi++)
                ldmatrix_x4(ah[mi], aH + (uint32_t)((mi * 16 * SR2) * 2) + koff);
            #pragma unroll
            for (int ni = 0; ni < 4; ni++)
                ldmatrix_x2(bh[ni], bH + (uint32_t)((ni * 8 * SR2) * 2) + koff);
            #pragma unroll
            for (int mi = 0; mi < 4; mi++)
                #pragma unroll
                for (int ni = 0; ni < 4; ni++)
                    mma_bf16(acc[mi][ni], ah[mi], bh[ni]);     // Ahi*Bhi

            uint32_t bl[4][2];
            #pragma unroll
            for (int ni = 0; ni < 4; ni++)
                ldmatrix_x2(bl[ni], bL + (uint32_t)((ni * 8 * SR2) * 2) + koff);
            #pragma unroll
            for (int mi = 0; mi < 4; mi++)
                #pragma unroll
                for (int ni = 0; ni < 4; ni++)
                    mma_bf16(acc[mi][ni], ah[mi], bl[ni]);     // Ahi*Blo

            uint32_t al[4][4];
            #pragma unroll
            for (int mi = 0; mi < 4; mi++)
                ldmatrix_x4(al[mi], aL + (uint32_t)((mi * 16 * SR2) * 2) + koff);
            #pragma unroll
            for (int mi = 0; mi < 4; mi++)
                #pragma unroll
                for (int ni = 0; ni < 4; ni++)
                    mma_bf16(acc[mi][ni], al[mi], bh[ni]);     // Alo*Bhi
        }
        __syncthreads();
    }

    // ---- epilogue: -log(1-p) over valid pairs, 8 values per __logf ----
    const int rq = lane >> 2;
    const int cq = (lane & 3) << 1;
    float lsum = 0.f;
    #pragma unroll
    for (int mi = 0; mi < 4; mi++) {
        const int rA = row0 + m_base + mi * 16 + rq;
        #pragma unroll
        for (int np = 0; np < 2; np++) {
            float prod = 1.0f;
            #pragma unroll
            for (int nj = 0; nj < 2; nj++) {
                const int ni = np * 2 + nj;
                const int cA = col0 + n_base + ni * 8 + cq;
                #pragma unroll
                for (int q = 0; q < 4; q++) {
                    const int r = rA + ((q >> 1) << 3);
                    const int c = cA + (q & 1);
                    float p = acc[mi][ni][q];
                    p = fminf(fmaxf(p, 1e-8f), 1.0f - 1e-8f);
                    const float x = (r < nr && c < nc) ? (1.0f - p) : 1.0f;
                    prod *= x;
                }
            }
            lsum -= __logf(prod);
        }
    }
    #pragma unroll
    for (int o = 16; o; o >>= 1) lsum += __shfl_xor_sync(0xffffffffu, lsum, o);
    if (lane == 0) wsum[wid] = lsum;
    __syncthreads();
    if (wid == 0) {
        float s = (lane < 8) ? wsum[lane] : 0.f;
        #pragma unroll
        for (int o = 4; o; o >>= 1) s += __shfl_xor_sync(0xffffffffu, s, o);
        if (lane == 0) atomicAdd(&g_numer, (double)s);
    }
}

// ---------------- finalize: chain+state reset, result ------------------------
__global__ void finalize_kernel(float* __restrict__ out, int n) {
    const int bk = blockIdx.x;
    if (bk < 64) {
        // unconditional chain reset: stale ids map to already-zero entries
        const int q = bk >> 3;
        const int i = ((bk & 7) << 8) + threadIdx.x;   // covers [0, SEQ)
        g_chead[q][g_col_id[q][i]] = 0;
        return;
    }
    // bk == 64: compute output, then reset counters/numer (block-local)
    __shared__ double s_res;
    if (threadIdx.x == 0) {
        double denom = 0.0;
        #pragma unroll
        for (int q = 0; q < BATCH; q++)
            denom += (double)g_nrows[q] * (double)g_ncols[q];
        s_res = g_numer / (denom + 1e-8);
        g_numer = 0.0;
        #pragma unroll
        for (int q = 0; q < BATCH; q++) { g_nrows[q] = 0; g_ncols[q] = 0; }
    }
    __syncthreads();
    float r = (float)s_res;
    for (int i = threadIdx.x; i < n; i += blockDim.x) out[i] = r;
}

// ---------------- launch ------------------------------------------------------
extern "C" void kernel_launch(void* const* d_in, const int* in_sizes, int n_in,
                              void* d_out, int out_size) {
    const int*           ids  = (const int*)d_in[0];
    const unsigned char* tf   = (const unsigned char*)d_in[1];
    const unsigned char* act  = (const unsigned char*)d_in[2];
    const int*           keys = (const int*)d_in[3];
    const float*         u    = (const float*)d_in[4];
    const float*         v    = (const float*)d_in[5];
    const int M = in_sizes[3];

    prep_kernel<<<64, 256>>>(ids, tf, act);
    dim3 grid(SEQ / 128, SEQ / 128, BATCH + 1);   // z==0 -> correction blocks
    main_kernel<<<grid, 256>>>(u, v, keys, M);
    finalize_kernel<<<65, 256>>>((float*)d_out, out_size);
}